// round 2
// baseline (speedup 1.0000x reference)
#include <cuda_runtime.h>
#include <math.h>

// Problem shape (fixed by the dataset)
#define B_ROWS 4096
#define K_COLS 256
#define D_DIM  128

// Tiling
#define BM 64
#define BK 64
#define PT_STRIDE 66   // padded d-major stride for p/a tiles (even -> 8B aligned float2)

// Dynamic smem: xs[BM][128] + pt[128][66] + at[128][66]
#define SMEM_FLOATS (BM * D_DIM + 2 * D_DIM * PT_STRIDE)
#define SMEM_BYTES  (SMEM_FLOATS * 4)

#define MIN_NORM 1e-15f

// Per-k / per-b precomputed scalars (device globals: no allocations allowed)
__device__ float g_y2[B_ROWS];   // |x_b|^2
__device__ float g_p2[K_COLS];   // |p_k|^2
__device__ float g_pa[K_COLS];   // p_k . a_k
__device__ float g_an[K_COLS];   // max(||a_k||, 1e-15)

// ---------------------------------------------------------------------------
// packed fp32x2 helpers (sm_103a FFMA2 is only reachable via PTX fma.rn.f32x2)
// ---------------------------------------------------------------------------
__device__ __forceinline__ unsigned long long fma2(unsigned long long a,
                                                   unsigned long long b,
                                                   unsigned long long c) {
    unsigned long long d;
    asm("fma.rn.f32x2 %0, %1, %2, %3;" : "=l"(d) : "l"(a), "l"(b), "l"(c));
    return d;
}

__device__ __forceinline__ unsigned long long pack_dup(float v) {
    unsigned long long r;
    unsigned int u = __float_as_uint(v);
    asm("mov.b64 %0, {%1, %1};" : "=l"(r) : "r"(u));
    return r;
}

__device__ __forceinline__ void unpack2(unsigned long long v, float& lo, float& hi) {
    unsigned int a, b;
    asm("mov.b64 {%0, %1}, %2;" : "=r"(a), "=r"(b) : "l"(v));
    lo = __uint_as_float(a);
    hi = __uint_as_float(b);
}

// ---------------------------------------------------------------------------
// Precompute kernel: blocks 0..15 -> y2 for 4096 rows; block 16 -> k stats
// ---------------------------------------------------------------------------
__global__ void mobius_pre_kernel(const float* __restrict__ x,
                                  const float* __restrict__ p,
                                  const float* __restrict__ a) {
    int t = threadIdx.x;
    if (blockIdx.x < 16) {
        int row = blockIdx.x * 256 + t;
        const float4* xr = (const float4*)(x + row * D_DIM);
        float s = 0.f;
#pragma unroll
        for (int i = 0; i < D_DIM / 4; i++) {
            float4 v = xr[i];
            s += v.x * v.x + v.y * v.y + v.z * v.z + v.w * v.w;
        }
        g_y2[row] = s;
    } else {
        int k = t;  // 256 threads, 256 k
        const float4* pr = (const float4*)(p + k * D_DIM);
        const float4* ar = (const float4*)(a + k * D_DIM);
        float p2 = 0.f, pa = 0.f, a2 = 0.f;
#pragma unroll
        for (int i = 0; i < D_DIM / 4; i++) {
            float4 pv = pr[i];
            float4 av = ar[i];
            p2 += pv.x * pv.x + pv.y * pv.y + pv.z * pv.z + pv.w * pv.w;
            pa += pv.x * av.x + pv.y * av.y + pv.z * av.z + pv.w * av.w;
            a2 += av.x * av.x + av.y * av.y + av.z * av.z + av.w * av.w;
        }
        g_p2[k] = p2;
        g_pa[k] = pa;
        g_an[k] = fmaxf(sqrtf(a2), MIN_NORM);
    }
}

// ---------------------------------------------------------------------------
// Scalar epilogue: all Mobius/arcsinh math from the reduced scalars
// ---------------------------------------------------------------------------
__device__ __forceinline__ float mobius_epilogue(float px, float xa, float y2,
                                                 float p2, float pa, float an) {
    // mobius_add(-p, x, c=1):
    //   alpha = 1 - 2*px + y2 ; beta = 1 - p2 ; den_m = 1 - 2*px + p2*y2
    float alpha = 1.f - 2.f * px + y2;
    float beta  = 1.f - p2;
    float den_m = fmaxf(fmaf(p2, y2, 1.f - 2.f * px), MIN_NORM);
    float inv   = 1.f / den_m;

    float mdota = (beta * xa - alpha * pa) * inv;                    // mpx . a
    float msq   = (alpha * alpha * p2 - 2.f * alpha * beta * px
                   + beta * beta * y2) * inv * inv;                  // |mpx|^2
    msq = fmaxf(msq, MIN_NORM);

    float den_f = fmaxf((1.f - msq) * an, MIN_NORM);
    float z = 2.f * mdota / den_f;
    return 2.f * an * asinhf(z);
}

// ---------------------------------------------------------------------------
// Main tiled kernel: per block a 64(b) x 64(k) tile, full D=128 in smem.
// Each thread: 4 b-rows x 4 k-cols (2 packed float2 k-pairs), FFMA2 inner loop.
// ---------------------------------------------------------------------------
extern __shared__ float smem[];

__global__ void __launch_bounds__(256)
mobius_mlr_kernel(const float* __restrict__ x,
                  const float* __restrict__ p,
                  const float* __restrict__ a,
                  float* __restrict__ out) {
    float* xs = smem;                       // [BM][128], b-major
    float* pt = smem + BM * D_DIM;          // [128][PT_STRIDE], d-major (transposed)
    float* at = pt + D_DIM * PT_STRIDE;     // [128][PT_STRIDE]

    const int tid = threadIdx.x;
    const int kb  = blockIdx.x * BK;
    const int bb  = blockIdx.y * BM;

    // ---- load x tile (coalesced float4) ----
    const float4* x4 = (const float4*)x;
#pragma unroll
    for (int it = 0; it < (BM * (D_DIM / 4)) / 256; it++) {
        int idx = tid + it * 256;
        int row = idx >> 5;          // 32 float4 per row
        int c   = idx & 31;
        ((float4*)xs)[row * 32 + c] = x4[(bb + row) * 32 + c];
    }

    // ---- load p/a tiles, transposed to d-major (coalesced global reads) ----
    const float4* p4 = (const float4*)p;
    const float4* a4 = (const float4*)a;
#pragma unroll
    for (int it = 0; it < (BK * (D_DIM / 4)) / 256; it++) {
        int idx = tid + it * 256;
        int k = idx >> 5;
        int c = idx & 31;
        int d = c * 4;
        float4 v = p4[(kb + k) * 32 + c];
        pt[(d + 0) * PT_STRIDE + k] = v.x;
        pt[(d + 1) * PT_STRIDE + k] = v.y;
        pt[(d + 2) * PT_STRIDE + k] = v.z;
        pt[(d + 3) * PT_STRIDE + k] = v.w;
        float4 w = a4[(kb + k) * 32 + c];
        at[(d + 0) * PT_STRIDE + k] = w.x;
        at[(d + 1) * PT_STRIDE + k] = w.y;
        at[(d + 2) * PT_STRIDE + k] = w.z;
        at[(d + 3) * PT_STRIDE + k] = w.w;
    }
    __syncthreads();

    const int tx = tid & 15;   // k dimension: pairs at k = 2*tx + 32*jj
    const int ty = tid >> 4;   // b dimension: rows ty*4 .. ty*4+3

    unsigned long long accP[4][2];
    unsigned long long accA[4][2];
#pragma unroll
    for (int i = 0; i < 4; i++)
#pragma unroll
        for (int jj = 0; jj < 2; jj++) { accP[i][jj] = 0ull; accA[i][jj] = 0ull; }

    const int koff0 = 2 * tx;
    const int koff1 = 2 * tx + 32;

#pragma unroll 8
    for (int d = 0; d < D_DIM; d++) {
        unsigned long long xp[4];
#pragma unroll
        for (int i = 0; i < 4; i++) {
            float xv = xs[(ty * 4 + i) * D_DIM + d];
            xp[i] = pack_dup(xv);
        }
        const float* ptd = pt + d * PT_STRIDE;
        const float* atd = at + d * PT_STRIDE;
        unsigned long long pv0 = *(const unsigned long long*)(ptd + koff0);
        unsigned long long pv1 = *(const unsigned long long*)(ptd + koff1);
        unsigned long long av0 = *(const unsigned long long*)(atd + koff0);
        unsigned long long av1 = *(const unsigned long long*)(atd + koff1);
#pragma unroll
        for (int i = 0; i < 4; i++) {
            accP[i][0] = fma2(xp[i], pv0, accP[i][0]);
            accP[i][1] = fma2(xp[i], pv1, accP[i][1]);
            accA[i][0] = fma2(xp[i], av0, accA[i][0]);
            accA[i][1] = fma2(xp[i], av1, accA[i][1]);
        }
    }

    // ---- epilogue ----
    float y2v[4];
#pragma unroll
    for (int i = 0; i < 4; i++) y2v[i] = g_y2[bb + ty * 4 + i];

#pragma unroll
    for (int jj = 0; jj < 2; jj++) {
        int kk = kb + 2 * tx + 32 * jj;
        float2 p2p = *(const float2*)&g_p2[kk];
        float2 pap = *(const float2*)&g_pa[kk];
        float2 anp = *(const float2*)&g_an[kk];
#pragma unroll
        for (int i = 0; i < 4; i++) {
            float pxl, pxh, xal, xah;
            unpack2(accP[i][jj], pxl, pxh);
            unpack2(accA[i][jj], xal, xah);
            float2 o;
            o.x = mobius_epilogue(pxl, xal, y2v[i], p2p.x, pap.x, anp.x);
            o.y = mobius_epilogue(pxh, xah, y2v[i], p2p.y, pap.y, anp.y);
            *(float2*)&out[(bb + ty * 4 + i) * K_COLS + kk] = o;
        }
    }
}

// ---------------------------------------------------------------------------
extern "C" void kernel_launch(void* const* d_in, const int* in_sizes, int n_in,
                              void* d_out, int out_size) {
    const float* x = (const float*)d_in[0];   // (4096, 128)
    const float* p = (const float*)d_in[1];   // (256, 128)
    const float* a = (const float*)d_in[2];   // (256, 128)
    float* out = (float*)d_out;               // (4096, 256)

    cudaFuncSetAttribute(mobius_mlr_kernel,
                         cudaFuncAttributeMaxDynamicSharedMemorySize, SMEM_BYTES);

    mobius_pre_kernel<<<17, 256>>>(x, p, a);
    dim3 grid(K_COLS / BK, B_ROWS / BM);
    mobius_mlr_kernel<<<grid, 256, SMEM_BYTES>>>(x, p, a, out);
}

// round 3
// speedup vs baseline: 1.1989x; 1.1989x over previous
#include <cuda_runtime.h>
#include <math.h>

#define B_ROWS 4096
#define K_COLS 256
#define D_DIM  128

#define BM 64
#define BK 64
#define XS_STRIDE 132            // padded b-major x tile stride (floats)
#define MIN_NORM 1e-15f

typedef unsigned long long ull;

// smem layout (floats)
#define OFF_PT   0                        // [128][64] swizzled d-major p
#define OFF_AT   (OFF_PT + 128 * 64)      // [128][64] swizzled d-major a
#define OFF_XS   (OFF_AT + 128 * 64)      // [64][132] b-major x
#define OFF_Y2   (OFF_XS + BM * XS_STRIDE)
#define OFF_P2   (OFF_Y2 + 64)
#define OFF_PA   (OFF_P2 + 64)
#define OFF_AN   (OFF_PA + 64)
#define OFF_PP2  (OFF_AN + 64)            // [4][64] partials
#define OFF_PPA  (OFF_PP2 + 256)
#define OFF_PA2  (OFF_PPA + 256)
#define SMEM_FLOATS (OFF_PA2 + 256)
#define SMEM_BYTES  (SMEM_FLOATS * 4)

// ---------------------------------------------------------------------------
__device__ __forceinline__ ull fma2(ull a, ull b, ull c) {
    ull d;
    asm("fma.rn.f32x2 %0, %1, %2, %3;" : "=l"(d) : "l"(a), "l"(b), "l"(c));
    return d;
}
__device__ __forceinline__ ull dup(float v) {
    ull r;
    asm("mov.b64 %0, {%1, %1};" : "=l"(r) : "r"(__float_as_uint(v)));
    return r;
}
__device__ __forceinline__ void unpack2(ull v, float& lo, float& hi) {
    unsigned int a, b;
    asm("mov.b64 {%0, %1}, %2;" : "=r"(a), "=r"(b) : "l"(v));
    lo = __uint_as_float(a);
    hi = __uint_as_float(b);
}

// Scalar Mobius/arcsinh epilogue from reduced scalars
__device__ __forceinline__ float mobius_epi(float px, float xa, float y2,
                                            float p2, float pa, float an) {
    float alpha = 1.f - 2.f * px + y2;
    float beta  = 1.f - p2;
    float den_m = fmaxf(fmaf(p2, y2, 1.f - 2.f * px), MIN_NORM);
    float inv   = 1.f / den_m;
    float mdota = (beta * xa - alpha * pa) * inv;
    float msq   = (alpha * alpha * p2 - 2.f * alpha * beta * px
                   + beta * beta * y2) * inv * inv;
    msq = fmaxf(msq, MIN_NORM);
    float den_f = fmaxf((1.f - msq) * an, MIN_NORM);
    return 2.f * an * asinhf(2.f * mdota / den_f);
}

extern __shared__ float smem[];

__global__ void __launch_bounds__(256, 2)
mobius_mlr_kernel(const float* __restrict__ x,
                  const float* __restrict__ gp,
                  const float* __restrict__ ga,
                  float* __restrict__ out) {
    float* pt  = smem + OFF_PT;
    float* at  = smem + OFF_AT;
    float* xs  = smem + OFF_XS;
    float* y2s = smem + OFF_Y2;
    float* p2s = smem + OFF_P2;
    float* pas = smem + OFF_PA;
    float* ans = smem + OFF_AN;
    float* pp2 = smem + OFF_PP2;
    float* ppa = smem + OFF_PPA;
    float* pa2 = smem + OFF_PA2;

    const int tid = threadIdx.x;
    const int kb  = blockIdx.x * BK;
    const int bb  = blockIdx.y * BM;

    // ---- x tile: coalesced float4, b-major, stride 132 (conflict-free) ----
    {
        const float4* x4 = (const float4*)x;
#pragma unroll
        for (int it = 0; it < 8; it++) {
            int idx = tid + it * 256;
            int row = idx >> 5;
            int c   = idx & 31;
            *(float4*)(xs + row * XS_STRIDE + 4 * c) = x4[(bb + row) * 32 + c];
        }
    }

    // ---- p/a tiles: transpose to swizzled d-major  k' = k ^ (((d>>1)&7)<<2)
    // warp handles a row-pair; half-warp reads one 128B-contiguous chunk.
    // stores are 2-way conflicted (one-time, small).
    {
        const int l  = tid & 31;
        const int w  = tid >> 5;
        const int hk = l >> 4;
        const int m  = l & 15;
        const int fsw = (m & 7) << 2;
        for (int task = w; task < 64; task += 8) {
            const int isA = task >> 5;
            const int k   = ((task & 31) << 1) + hk;
            const float* src = (isA ? ga : gp) + (kb + k) * D_DIM;
            float* dst = isA ? at : pt;
            const int kc = k ^ fsw;
#pragma unroll
            for (int dc = 0; dc < 4; dc++) {
                float2 v = *(const float2*)(src + dc * 32 + 2 * m);
                int d0 = dc * 32 + 2 * m;
                dst[d0 * 64 + kc]       = v.x;
                dst[(d0 + 1) * 64 + kc] = v.y;
            }
        }
    }
    __syncthreads();

    // ---- stats: y2 per row (shfl over lane-quads), k partials over d-segments
    {
        const int r = tid >> 2;
        const int q = tid & 3;
        float s = 0.f;
#pragma unroll
        for (int j = 0; j < 32; j++) {
            float v = xs[r * XS_STRIDE + q + 4 * j];
            s = fmaf(v, v, s);
        }
        s += __shfl_xor_sync(0xffffffffu, s, 1);
        s += __shfl_xor_sync(0xffffffffu, s, 2);
        if (q == 0) y2s[r] = s;

        const int k   = tid & 63;
        const int seg = tid >> 6;
        float p2 = 0.f, pa = 0.f, a2 = 0.f;
#pragma unroll
        for (int j = 0; j < 32; j++) {
            int d  = seg * 32 + j;
            int kc = k ^ (((d >> 1) & 7) << 2);
            float pv = pt[d * 64 + kc];
            float av = at[d * 64 + kc];
            p2 = fmaf(pv, pv, p2);
            pa = fmaf(pv, av, pa);
            a2 = fmaf(av, av, a2);
        }
        pp2[seg * 64 + k] = p2;
        ppa[seg * 64 + k] = pa;
        pa2[seg * 64 + k] = a2;
    }
    __syncthreads();
    if (tid < 64) {
        float p2 = pp2[tid] + pp2[64 + tid] + pp2[128 + tid] + pp2[192 + tid];
        float pa = ppa[tid] + ppa[64 + tid] + ppa[128 + tid] + ppa[192 + tid];
        float a2 = pa2[tid] + pa2[64 + tid] + pa2[128 + tid] + pa2[192 + tid];
        p2s[tid] = p2;
        pas[tid] = pa;
        ans[tid] = fmaxf(sqrtf(a2), MIN_NORM);
    }
    __syncthreads();

    // ---- main loop: thread tile 2 rows x 8 k (two float4 k-groups) ----
    const int tx  = tid & 7;
    const int ty  = tid >> 3;
    const int tx4 = tx * 4;
    const float* xr0 = xs + (ty * 2) * XS_STRIDE;
    const float* xr1 = xr0 + XS_STRIDE;

    ull aP[2][2][2];   // [row][k-group][pair-half]
    ull aA[2][2][2];
#pragma unroll
    for (int i = 0; i < 2; i++)
#pragma unroll
        for (int g = 0; g < 2; g++)
#pragma unroll
            for (int h = 0; h < 2; h++) { aP[i][g][h] = 0ull; aA[i][g][h] = 0ull; }

    for (int db = 0; db < D_DIM; db += 16) {
#pragma unroll
        for (int j = 0; j < 8; j++) {
            const int d  = db + 2 * j;
            const int c0 = tx4 ^ (j << 2);      // swizzled k-block, compile-time XOR
            float2 xv0 = *(const float2*)(xr0 + d);
            float2 xv1 = *(const float2*)(xr1 + d);
#pragma unroll
            for (int dd = 0; dd < 2; dd++) {
                const float* ptd = pt + (d + dd) * 64;
                const float* atd = at + (d + dd) * 64;
                ulonglong2 pg0 = *(const ulonglong2*)(ptd + c0);
                ulonglong2 pg1 = *(const ulonglong2*)(ptd + c0 + 32);
                ulonglong2 ag0 = *(const ulonglong2*)(atd + c0);
                ulonglong2 ag1 = *(const ulonglong2*)(atd + c0 + 32);
                ull x0 = dup(dd ? xv0.y : xv0.x);
                ull x1 = dup(dd ? xv1.y : xv1.x);
                aP[0][0][0] = fma2(x0, pg0.x, aP[0][0][0]);
                aP[0][0][1] = fma2(x0, pg0.y, aP[0][0][1]);
                aP[0][1][0] = fma2(x0, pg1.x, aP[0][1][0]);
                aP[0][1][1] = fma2(x0, pg1.y, aP[0][1][1]);
                aP[1][0][0] = fma2(x1, pg0.x, aP[1][0][0]);
                aP[1][0][1] = fma2(x1, pg0.y, aP[1][0][1]);
                aP[1][1][0] = fma2(x1, pg1.x, aP[1][1][0]);
                aP[1][1][1] = fma2(x1, pg1.y, aP[1][1][1]);
                aA[0][0][0] = fma2(x0, ag0.x, aA[0][0][0]);
                aA[0][0][1] = fma2(x0, ag0.y, aA[0][0][1]);
                aA[0][1][0] = fma2(x0, ag1.x, aA[0][1][0]);
                aA[0][1][1] = fma2(x0, ag1.y, aA[0][1][1]);
                aA[1][0][0] = fma2(x1, ag0.x, aA[1][0][0]);
                aA[1][0][1] = fma2(x1, ag0.y, aA[1][0][1]);
                aA[1][1][0] = fma2(x1, ag1.x, aA[1][1][0]);
                aA[1][1][1] = fma2(x1, ag1.y, aA[1][1][1]);
            }
        }
    }

    // ---- epilogue: scalars from smem, float4 stores ----
    const int r0 = ty * 2;
    float y2v0 = y2s[r0];
    float y2v1 = y2s[r0 + 1];
#pragma unroll
    for (int i = 0; i < 2; i++) {
        float y2 = i ? y2v1 : y2v0;
#pragma unroll
        for (int g = 0; g < 2; g++) {
            const int kk = tx4 + 32 * g;
            float4 p2v = *(const float4*)(p2s + kk);
            float4 pav = *(const float4*)(pas + kk);
            float4 anv = *(const float4*)(ans + kk);
            float px0, px1, px2, px3, xa0, xa1, xa2, xa3;
            unpack2(aP[i][g][0], px0, px1);
            unpack2(aP[i][g][1], px2, px3);
            unpack2(aA[i][g][0], xa0, xa1);
            unpack2(aA[i][g][1], xa2, xa3);
            float4 o;
            o.x = mobius_epi(px0, xa0, y2, p2v.x, pav.x, anv.x);
            o.y = mobius_epi(px1, xa1, y2, p2v.y, pav.y, anv.y);
            o.z = mobius_epi(px2, xa2, y2, p2v.z, pav.z, anv.z);
            o.w = mobius_epi(px3, xa3, y2, p2v.w, pav.w, anv.w);
            *(float4*)(out + (bb + r0 + i) * K_COLS + kb + kk) = o;
        }
    }
}

// ---------------------------------------------------------------------------
extern "C" void kernel_launch(void* const* d_in, const int* in_sizes, int n_in,
                              void* d_out, int out_size) {
    const float* x = (const float*)d_in[0];   // (4096, 128)
    const float* p = (const float*)d_in[1];   // (256, 128)
    const float* a = (const float*)d_in[2];   // (256, 128)
    float* out = (float*)d_out;               // (4096, 256)

    cudaFuncSetAttribute(mobius_mlr_kernel,
                         cudaFuncAttributeMaxDynamicSharedMemorySize, SMEM_BYTES);

    dim3 grid(K_COLS / BK, B_ROWS / BM);
    mobius_mlr_kernel<<<grid, 256, SMEM_BYTES>>>(x, p, a, out);
}

// round 6
// speedup vs baseline: 1.8600x; 1.5514x over previous
#include <cuda_runtime.h>
#include <cuda_bf16.h>
#include <math.h>
#include <cstdint>

typedef unsigned long long ull;

#define B_ROWS 4096
#define K_COLS 256
#define D_DIM  128
#define BM     128       // x-rows per CTA
#define BKH    64        // hyperplanes per CTA (=> 128 interleaved W rows)
#define THREADS 256
#define MIN_NORM 1e-15f

#define TSTRIDE 136      // bf16 elems per tile row (272 B): >=128 data + pad, 16B-mult,
                         // stride mod 128B-group = 1 -> conflict-free ldmatrix
#define ROW_BYTES (TSTRIDE * 2)
#define TILE_BYTES (128 * ROW_BYTES)

// smem byte offsets
#define OFF_Y2   0                       // 128 f32
#define OFF_P2   512                     // 64 f32
#define OFF_PA   768
#define OFF_AN   1024
#define OFF_XHI  2048
#define OFF_XLO  (OFF_XHI + TILE_BYTES)
#define OFF_WHI  (OFF_XLO + TILE_BYTES)
#define OFF_WLO  (OFF_WHI + TILE_BYTES)
#define SMEM_BYTES (OFF_WLO + TILE_BYTES)

// ---------------------------------------------------------------------------
__device__ __forceinline__ uint32_t smem_u32(const void* p) {
    uint32_t a;
    asm("{ .reg .u64 t; cvta.to.shared.u64 t, %1; cvt.u32.u64 %0, t; }"
        : "=r"(a) : "l"(p));
    return a;
}

__device__ __forceinline__ void ldsm_x4(uint32_t* r, uint32_t addr) {
    asm volatile("ldmatrix.sync.aligned.m8n8.x4.shared.b16 {%0,%1,%2,%3}, [%4];"
                 : "=r"(r[0]), "=r"(r[1]), "=r"(r[2]), "=r"(r[3]) : "r"(addr));
}

__device__ __forceinline__ void mma_bf16(float* c, const uint32_t* a, const uint32_t* b) {
    asm volatile(
        "mma.sync.aligned.m16n8k16.row.col.f32.bf16.bf16.f32 "
        "{%0,%1,%2,%3}, {%4,%5,%6,%7}, {%8,%9}, {%0,%1,%2,%3};"
        : "+f"(c[0]), "+f"(c[1]), "+f"(c[2]), "+f"(c[3])
        : "r"(a[0]), "r"(a[1]), "r"(a[2]), "r"(a[3]), "r"(b[0]), "r"(b[1]));
}

// fp32 -> bf16 hi/lo split, 4 values packed into two 8-byte words
__device__ __forceinline__ void cvt4(const float4 v, ull& hi, ull& lo) {
    __nv_bfloat16 h0 = __float2bfloat16(v.x), h1 = __float2bfloat16(v.y);
    __nv_bfloat16 h2 = __float2bfloat16(v.z), h3 = __float2bfloat16(v.w);
    __nv_bfloat16 l0 = __float2bfloat16(v.x - __bfloat162float(h0));
    __nv_bfloat16 l1 = __float2bfloat16(v.y - __bfloat162float(h1));
    __nv_bfloat16 l2 = __float2bfloat16(v.z - __bfloat162float(h2));
    __nv_bfloat16 l3 = __float2bfloat16(v.w - __bfloat162float(h3));
    uint32_t hA = (uint32_t)__bfloat16_as_ushort(h0) | ((uint32_t)__bfloat16_as_ushort(h1) << 16);
    uint32_t hB = (uint32_t)__bfloat16_as_ushort(h2) | ((uint32_t)__bfloat16_as_ushort(h3) << 16);
    uint32_t lA = (uint32_t)__bfloat16_as_ushort(l0) | ((uint32_t)__bfloat16_as_ushort(l1) << 16);
    uint32_t lB = (uint32_t)__bfloat16_as_ushort(l2) | ((uint32_t)__bfloat16_as_ushort(l3) << 16);
    hi = (ull)hA | ((ull)hB << 32);
    lo = (ull)lA | ((ull)lB << 32);
}

__device__ __forceinline__ float mobius_epi(float px, float xa, float y2,
                                            float p2, float pa, float an) {
    float alpha = 1.f - 2.f * px + y2;
    float beta  = 1.f - p2;
    float den_m = fmaxf(fmaf(p2, y2, 1.f - 2.f * px), MIN_NORM);
    float inv   = __fdividef(1.f, den_m);
    float mdota = (beta * xa - alpha * pa) * inv;
    float msq   = (alpha * alpha * p2 - 2.f * alpha * beta * px
                   + beta * beta * y2) * inv * inv;
    msq = fmaxf(msq, MIN_NORM);
    float den_f = fmaxf((1.f - msq) * an, MIN_NORM);
    return 2.f * an * asinhf(__fdividef(2.f * mdota, den_f));
}

// ---------------------------------------------------------------------------
extern __shared__ char smem[];

__global__ void __launch_bounds__(THREADS, 1)
mobius_mlr_mma_kernel(const float* __restrict__ x,
                      const float* __restrict__ gp,
                      const float* __restrict__ ga,
                      float* __restrict__ out) {
    const uint32_t sb  = smem_u32(smem);
    const int tid  = threadIdx.x;
    const int wid  = tid >> 5;
    const int lane = tid & 31;
    const int kb   = blockIdx.x * BKH;
    const int bb   = blockIdx.y * BM;

    float* y2s = (float*)(smem + OFF_Y2);
    float* p2s = (float*)(smem + OFF_P2);
    float* pas = (float*)(smem + OFF_PA);
    float* ans = (float*)(smem + OFF_AN);

    // ---- X tile: fp32 coalesced load, bf16 hi/lo split, y2 via warp reduce
    {
        const float4* x4 = (const float4*)(x + (size_t)bb * D_DIM);
#pragma unroll
        for (int i = 0; i < 16; i++) {
            int idx = tid + i * 256;        // one warp covers exactly one row
            int row = idx >> 5;
            int c4  = idx & 31;
            float4 v = x4[idx];
            ull hi, lo;
            cvt4(v, hi, lo);
            uint32_t off = (uint32_t)(row * ROW_BYTES + c4 * 8);
            *(ull*)(smem + OFF_XHI + off) = hi;
            *(ull*)(smem + OFF_XLO + off) = lo;
            float s = fmaf(v.x, v.x, fmaf(v.y, v.y, fmaf(v.z, v.z, v.w * v.w)));
            s += __shfl_xor_sync(0xffffffffu, s, 16);
            s += __shfl_xor_sync(0xffffffffu, s, 8);
            s += __shfl_xor_sync(0xffffffffu, s, 4);
            s += __shfl_xor_sync(0xffffffffu, s, 2);
            s += __shfl_xor_sync(0xffffffffu, s, 1);
            if (lane == 0) y2s[row] = s;
        }
    }

    // ---- W tile: rows interleaved (p_k, a_k), bf16 hi/lo split ----
    {
#pragma unroll
        for (int i = 0; i < 16; i++) {
            int idx = tid + i * 256;
            int row = idx >> 5;             // 0..127: 2j = p_kj, 2j+1 = a_kj
            int c4  = idx & 31;
            int kk  = kb + (row >> 1);
            const float4* src = (const float4*)(((row & 1) ? ga : gp) + (size_t)kk * D_DIM);
            float4 v = src[c4];
            ull hi, lo;
            cvt4(v, hi, lo);
            uint32_t off = (uint32_t)(row * ROW_BYTES + c4 * 8);
            *(ull*)(smem + OFF_WHI + off) = hi;
            *(ull*)(smem + OFF_WLO + off) = lo;
        }
    }

    // ---- exact fp32 per-k scalars (L2-hot reads) ----
    if (tid < BKH) {
        const float4* pr = (const float4*)(gp + (size_t)(kb + tid) * D_DIM);
        const float4* ar = (const float4*)(ga + (size_t)(kb + tid) * D_DIM);
        float p2 = 0.f, pa = 0.f, a2 = 0.f;
#pragma unroll
        for (int i = 0; i < 32; i++) {
            float4 pv = pr[i], av = ar[i];
            p2 = fmaf(pv.x, pv.x, fmaf(pv.y, pv.y, fmaf(pv.z, pv.z, fmaf(pv.w, pv.w, p2))));
            pa = fmaf(pv.x, av.x, fmaf(pv.y, av.y, fmaf(pv.z, av.z, fmaf(pv.w, av.w, pa))));
            a2 = fmaf(av.x, av.x, fmaf(av.y, av.y, fmaf(av.z, av.z, fmaf(av.w, av.w, a2))));
        }
        p2s[tid] = p2;
        pas[tid] = pa;
        ans[tid] = fmaxf(sqrtf(a2), MIN_NORM);
    }
    __syncthreads();

    // ---- warp tiling: wm = row-block (32 rows), wn = col-block (64 W-cols)
    const int wm = wid & 3;
    const int wn = wid >> 2;
    const int rm = wm * 32;
    const int cn = wn * 64;

    float acc[2][8][4];
#pragma unroll
    for (int ma = 0; ma < 2; ma++)
#pragma unroll
        for (int j = 0; j < 8; j++)
#pragma unroll
            for (int q = 0; q < 4; q++) acc[ma][j][q] = 0.f;

    // ldmatrix lane address components
    const int a_row = lane & 15;             // rows 0-15 of m16 tile
    const int a_kh  = (lane >> 4) * 8;       // k-half select
    const int b_g   = lane >> 3;             // 4 groups
    const int b_row = lane & 7;
    const int b_joff = (b_g >> 1);           // atom within pair
    const int b_kh  = (b_g & 1) * 8;

#pragma unroll
    for (int ks = 0; ks < 8; ks++) {
        const int kk = ks * 16;
        uint32_t Ahi[2][4], Alo[2][4], Bhi[8][2], Blo[8][2];
#pragma unroll
        for (int ma = 0; ma < 2; ma++) {
            uint32_t aoff = (uint32_t)((rm + ma * 16 + a_row) * ROW_BYTES
                                       + (kk + a_kh) * 2);
            ldsm_x4(Ahi[ma], sb + OFF_XHI + aoff);
            ldsm_x4(Alo[ma], sb + OFF_XLO + aoff);
        }
#pragma unroll
        for (int jp = 0; jp < 4; jp++) {     // atom pairs (2j, 2j+1)
            uint32_t boff = (uint32_t)((cn + (2 * jp + b_joff) * 8 + b_row) * ROW_BYTES
                                       + (kk + b_kh) * 2);
            uint32_t r[4];
            ldsm_x4(r, sb + OFF_WHI + boff);
            Bhi[2 * jp][0] = r[0]; Bhi[2 * jp][1] = r[1];
            Bhi[2 * jp + 1][0] = r[2]; Bhi[2 * jp + 1][1] = r[3];
            ldsm_x4(r, sb + OFF_WLO + boff);
            Blo[2 * jp][0] = r[0]; Blo[2 * jp][1] = r[1];
            Blo[2 * jp + 1][0] = r[2]; Blo[2 * jp + 1][1] = r[3];
        }
#pragma unroll
        for (int ma = 0; ma < 2; ma++) {
#pragma unroll
            for (int j = 0; j < 8; j++) {
                mma_bf16(acc[ma][j], Ahi[ma], Bhi[j]);
                mma_bf16(acc[ma][j], Ahi[ma], Blo[j]);
                mma_bf16(acc[ma][j], Alo[ma], Bhi[j]);
            }
        }
    }

    // ---- epilogue: D-frag lane holds (px, xa) pairs directly ----
    const int l4 = lane >> 2;
    const int lm = lane & 3;
#pragma unroll
    for (int ma = 0; ma < 2; ma++) {
        const int r0 = rm + ma * 16 + l4;
        const int r1 = r0 + 8;
        const float y20 = y2s[r0];
        const float y21 = y2s[r1];
        float* o0 = out + (size_t)(bb + r0) * K_COLS + kb;
        float* o1 = out + (size_t)(bb + r1) * K_COLS + kb;
#pragma unroll
        for (int j = 0; j < 8; j++) {
            const int kl = wn * 32 + j * 4 + lm;
            const float p2 = p2s[kl], pa = pas[kl], an = ans[kl];
            o0[kl] = mobius_epi(acc[ma][j][0], acc[ma][j][1], y20, p2, pa, an);
            o1[kl] = mobius_epi(acc[ma][j][2], acc[ma][j][3], y21, p2, pa, an);
        }
    }
}

// ---------------------------------------------------------------------------
extern "C" void kernel_launch(void* const* d_in, const int* in_sizes, int n_in,
                              void* d_out, int out_size) {
    const float* x = (const float*)d_in[0];   // (4096, 128)
    const float* p = (const float*)d_in[1];   // (256, 128)
    const float* a = (const float*)d_in[2];   // (256, 128)
    float* out = (float*)d_out;               // (4096, 256)

    cudaFuncSetAttribute(mobius_mlr_mma_kernel,
                         cudaFuncAttributeMaxDynamicSharedMemorySize, SMEM_BYTES);

    dim3 grid(K_COLS / BKH, B_ROWS / BM);     // (4, 32) = 128 CTAs, one wave
    mobius_mlr_mma_kernel<<<grid, THREADS, SMEM_BYTES>>>(x, p, a, out);
}

// round 7
// speedup vs baseline: 1.9050x; 1.0242x over previous
#include <cuda_runtime.h>
#include <cuda_bf16.h>
#include <math.h>
#include <cstdint>

typedef unsigned long long ull;

#define B_ROWS 4096
#define K_COLS 256
#define D_DIM  128
#define BM     128       // x-rows per CTA
#define BKH    64        // hyperplanes per CTA (=> 128 interleaved W rows)
#define THREADS 512
#define MIN_NORM 1e-15f

#define TSTRIDE 136      // bf16 elems per tile row (272 B), conflict-free ldmatrix
#define ROW_BYTES (TSTRIDE * 2)
#define TILE_BYTES (128 * ROW_BYTES)

// smem byte offsets
#define OFF_Y2   0                       // 128 f32
#define OFF_P2   512                     // 64 f32
#define OFF_PA   768
#define OFF_AN   1024
#define OFF_XHI  2048
#define OFF_XLO  (OFF_XHI + TILE_BYTES)
#define OFF_WHI  (OFF_XLO + TILE_BYTES)
#define OFF_WLO  (OFF_WHI + TILE_BYTES)
#define SMEM_BYTES (OFF_WLO + TILE_BYTES)

// ---------------------------------------------------------------------------
__device__ __forceinline__ uint32_t smem_u32(const void* p) {
    uint32_t a;
    asm("{ .reg .u64 t; cvta.to.shared.u64 t, %1; cvt.u32.u64 %0, t; }"
        : "=r"(a) : "l"(p));
    return a;
}

__device__ __forceinline__ void ldsm_x4(uint32_t* r, uint32_t addr) {
    asm volatile("ldmatrix.sync.aligned.m8n8.x4.shared.b16 {%0,%1,%2,%3}, [%4];"
                 : "=r"(r[0]), "=r"(r[1]), "=r"(r[2]), "=r"(r[3]) : "r"(addr));
}

__device__ __forceinline__ void mma_bf16(float* c, const uint32_t* a, const uint32_t* b) {
    asm volatile(
        "mma.sync.aligned.m16n8k16.row.col.f32.bf16.bf16.f32 "
        "{%0,%1,%2,%3}, {%4,%5,%6,%7}, {%8,%9}, {%0,%1,%2,%3};"
        : "+f"(c[0]), "+f"(c[1]), "+f"(c[2]), "+f"(c[3])
        : "r"(a[0]), "r"(a[1]), "r"(a[2]), "r"(a[3]), "r"(b[0]), "r"(b[1]));
}

// fp32 -> bf16 hi/lo split, 4 values packed into two 8-byte words
__device__ __forceinline__ void cvt4(const float4 v, ull& hi, ull& lo) {
    __nv_bfloat16 h0 = __float2bfloat16(v.x), h1 = __float2bfloat16(v.y);
    __nv_bfloat16 h2 = __float2bfloat16(v.z), h3 = __float2bfloat16(v.w);
    __nv_bfloat16 l0 = __float2bfloat16(v.x - __bfloat162float(h0));
    __nv_bfloat16 l1 = __float2bfloat16(v.y - __bfloat162float(h1));
    __nv_bfloat16 l2 = __float2bfloat16(v.z - __bfloat162float(h2));
    __nv_bfloat16 l3 = __float2bfloat16(v.w - __bfloat162float(h3));
    uint32_t hA = (uint32_t)__bfloat16_as_ushort(h0) | ((uint32_t)__bfloat16_as_ushort(h1) << 16);
    uint32_t hB = (uint32_t)__bfloat16_as_ushort(h2) | ((uint32_t)__bfloat16_as_ushort(h3) << 16);
    uint32_t lA = (uint32_t)__bfloat16_as_ushort(l0) | ((uint32_t)__bfloat16_as_ushort(l1) << 16);
    uint32_t lB = (uint32_t)__bfloat16_as_ushort(l2) | ((uint32_t)__bfloat16_as_ushort(l3) << 16);
    hi = (ull)hA | ((ull)hB << 32);
    lo = (ull)lA | ((ull)lB << 32);
}

__device__ __forceinline__ float mobius_epi(float px, float xa, float y2,
                                            float p2, float pa, float an) {
    float alpha = 1.f - 2.f * px + y2;
    float beta  = 1.f - p2;
    float den_m = fmaxf(fmaf(p2, y2, 1.f - 2.f * px), MIN_NORM);
    float inv   = __fdividef(1.f, den_m);
    float mdota = (beta * xa - alpha * pa) * inv;
    float msq   = (alpha * alpha * p2 - 2.f * alpha * beta * px
                   + beta * beta * y2) * inv * inv;
    msq = fmaxf(msq, MIN_NORM);
    float den_f = fmaxf((1.f - msq) * an, MIN_NORM);
    return 2.f * an * asinhf(__fdividef(2.f * mdota, den_f));
}

// ---------------------------------------------------------------------------
extern __shared__ char smem[];

__global__ void __launch_bounds__(THREADS, 1)
mobius_mlr_mma_kernel(const float* __restrict__ x,
                      const float* __restrict__ gp,
                      const float* __restrict__ ga,
                      float* __restrict__ out) {
    const uint32_t sb  = smem_u32(smem);
    const int tid  = threadIdx.x;
    const int wid  = tid >> 5;
    const int lane = tid & 31;
    const int kb   = blockIdx.x * BKH;
    const int bb   = blockIdx.y * BM;

    float* y2s = (float*)(smem + OFF_Y2);
    float* p2s = (float*)(smem + OFF_P2);
    float* pas = (float*)(smem + OFF_PA);
    float* ans = (float*)(smem + OFF_AN);

    // ---- X tile: fp32 coalesced load, bf16 hi/lo split, y2 via warp reduce
    {
        const float4* x4 = (const float4*)(x + (size_t)bb * D_DIM);
#pragma unroll
        for (int i = 0; i < 8; i++) {
            int idx = tid + i * THREADS;    // one warp covers exactly one row
            int row = idx >> 5;
            int c4  = idx & 31;
            float4 v = x4[idx];
            ull hi, lo;
            cvt4(v, hi, lo);
            uint32_t off = (uint32_t)(row * ROW_BYTES + c4 * 8);
            *(ull*)(smem + OFF_XHI + off) = hi;
            *(ull*)(smem + OFF_XLO + off) = lo;
            float s = fmaf(v.x, v.x, fmaf(v.y, v.y, fmaf(v.z, v.z, v.w * v.w)));
            s += __shfl_xor_sync(0xffffffffu, s, 16);
            s += __shfl_xor_sync(0xffffffffu, s, 8);
            s += __shfl_xor_sync(0xffffffffu, s, 4);
            s += __shfl_xor_sync(0xffffffffu, s, 2);
            s += __shfl_xor_sync(0xffffffffu, s, 1);
            if (lane == 0) y2s[row] = s;
        }
    }

    // ---- W tile: rows interleaved (p_k, a_k), bf16 hi/lo split ----
    {
#pragma unroll
        for (int i = 0; i < 8; i++) {
            int idx = tid + i * THREADS;
            int row = idx >> 5;             // 0..127: 2j = p_kj, 2j+1 = a_kj
            int c4  = idx & 31;
            int kk  = kb + (row >> 1);
            const float4* src = (const float4*)(((row & 1) ? ga : gp) + (size_t)kk * D_DIM);
            float4 v = src[c4];
            ull hi, lo;
            cvt4(v, hi, lo);
            uint32_t off = (uint32_t)(row * ROW_BYTES + c4 * 8);
            *(ull*)(smem + OFF_WHI + off) = hi;
            *(ull*)(smem + OFF_WLO + off) = lo;
        }
    }

    // ---- exact fp32 per-k scalars (L2-hot reads) ----
    if (tid < BKH) {
        const float4* pr = (const float4*)(gp + (size_t)(kb + tid) * D_DIM);
        const float4* ar = (const float4*)(ga + (size_t)(kb + tid) * D_DIM);
        float p2 = 0.f, pa = 0.f, a2 = 0.f;
#pragma unroll
        for (int i = 0; i < 32; i++) {
            float4 pv = pr[i], av = ar[i];
            p2 = fmaf(pv.x, pv.x, fmaf(pv.y, pv.y, fmaf(pv.z, pv.z, fmaf(pv.w, pv.w, p2))));
            pa = fmaf(pv.x, av.x, fmaf(pv.y, av.y, fmaf(pv.z, av.z, fmaf(pv.w, av.w, pa))));
            a2 = fmaf(av.x, av.x, fmaf(av.y, av.y, fmaf(av.z, av.z, fmaf(av.w, av.w, a2))));
        }
        p2s[tid] = p2;
        pas[tid] = pa;
        ans[tid] = fmaxf(sqrtf(a2), MIN_NORM);
    }
    __syncthreads();

    // ---- warp tiling: 16 warps, warp tile 32 rows x 32 W-cols ----
    const int wm = wid & 3;          // row block (32 rows)
    const int wn = wid >> 2;         // col block (32 W-cols = 16 hyperplanes)
    const int rm = wm * 32;
    const int cn = wn * 32;

    float acc[2][4][4];
#pragma unroll
    for (int ma = 0; ma < 2; ma++)
#pragma unroll
        for (int j = 0; j < 4; j++)
#pragma unroll
            for (int q = 0; q < 4; q++) acc[ma][j][q] = 0.f;

    // ldmatrix lane address components
    const int a_row = lane & 15;             // rows 0-15 of m16 tile
    const int a_kh  = (lane >> 4) * 8;       // k-half select
    const int b_g   = lane >> 3;             // 4 groups
    const int b_row = lane & 7;
    const int b_joff = (b_g >> 1);           // atom within pair
    const int b_kh  = (b_g & 1) * 8;

#pragma unroll
    for (int ks = 0; ks < 8; ks++) {
        const int kk = ks * 16;
        uint32_t Ahi[2][4], Alo[2][4], Bhi[4][2], Blo[4][2];
#pragma unroll
        for (int ma = 0; ma < 2; ma++) {
            uint32_t aoff = (uint32_t)((rm + ma * 16 + a_row) * ROW_BYTES
                                       + (kk + a_kh) * 2);
            ldsm_x4(Ahi[ma], sb + OFF_XHI + aoff);
            ldsm_x4(Alo[ma], sb + OFF_XLO + aoff);
        }
#pragma unroll
        for (int jp = 0; jp < 2; jp++) {     // atom pairs (2j, 2j+1)
            uint32_t boff = (uint32_t)((cn + (2 * jp + b_joff) * 8 + b_row) * ROW_BYTES
                                       + (kk + b_kh) * 2);
            uint32_t r[4];
            ldsm_x4(r, sb + OFF_WHI + boff);
            Bhi[2 * jp][0] = r[0]; Bhi[2 * jp][1] = r[1];
            Bhi[2 * jp + 1][0] = r[2]; Bhi[2 * jp + 1][1] = r[3];
            ldsm_x4(r, sb + OFF_WLO + boff);
            Blo[2 * jp][0] = r[0]; Blo[2 * jp][1] = r[1];
            Blo[2 * jp + 1][0] = r[2]; Blo[2 * jp + 1][1] = r[3];
        }
#pragma unroll
        for (int ma = 0; ma < 2; ma++) {
#pragma unroll
            for (int j = 0; j < 4; j++) {
                mma_bf16(acc[ma][j], Ahi[ma], Bhi[j]);
                mma_bf16(acc[ma][j], Ahi[ma], Blo[j]);
                mma_bf16(acc[ma][j], Alo[ma], Bhi[j]);
            }
        }
    }

    // ---- epilogue: D-frag lane holds (px, xa) pairs directly ----
    const int l4 = lane >> 2;
    const int lm = lane & 3;
#pragma unroll
    for (int ma = 0; ma < 2; ma++) {
        const int r0 = rm + ma * 16 + l4;
        const int r1 = r0 + 8;
        const float y20 = y2s[r0];
        const float y21 = y2s[r1];
        float* o0 = out + (size_t)(bb + r0) * K_COLS + kb;
        float* o1 = out + (size_t)(bb + r1) * K_COLS + kb;
#pragma unroll
        for (int j = 0; j < 4; j++) {
            const int kl = wn * 16 + j * 4 + lm;
            const float p2 = p2s[kl], pa = pas[kl], an = ans[kl];
            o0[kl] = mobius_epi(acc[ma][j][0], acc[ma][j][1], y20, p2, pa, an);
            o1[kl] = mobius_epi(acc[ma][j][2], acc[ma][j][3], y21, p2, pa, an);
        }
    }
}

// ---------------------------------------------------------------------------
extern "C" void kernel_launch(void* const* d_in, const int* in_sizes, int n_in,
                              void* d_out, int out_size) {
    const float* x = (const float*)d_in[0];   // (4096, 128)
    const float* p = (const float*)d_in[1];   // (256, 128)
    const float* a = (const float*)d_in[2];   // (256, 128)
    float* out = (float*)d_out;               // (4096, 256)

    cudaFuncSetAttribute(mobius_mlr_mma_kernel,
                         cudaFuncAttributeMaxDynamicSharedMemorySize, SMEM_BYTES);

    dim3 grid(K_COLS / BKH, B_ROWS / BM);     // (4, 32) = 128 CTAs, one wave
    mobius_mlr_mma_kernel<<<grid, THREADS, SMEM_BYTES>>>(x, p, a, out);
}